// round 1
// baseline (speedup 1.0000x reference)
#include <cuda_runtime.h>
#include <math.h>

#define NB 4096
#define NC 512
#define NHW 196
#define NE 64
#define TOPK 8
#define ROWS 16

// scratch: pooled [B, C]  (8 MB) — __device__ global, no allocation
__device__ float g_pooled[NB * NC];

// ---------------------------------------------------------------------------
// Kernel 1: global average pool  [B, C, H, W] -> [B, C]
// One warp per (b,c) row: 196 contiguous floats = 49 float4 (784B, 16B-aligned)
// ---------------------------------------------------------------------------
__global__ __launch_bounds__(256) void pool_kernel(const float* __restrict__ x) {
    int warp = (blockIdx.x * 256 + threadIdx.x) >> 5;
    int lane = threadIdx.x & 31;
    if (warp >= NB * NC) return;

    const float4* row4 = reinterpret_cast<const float4*>(x + (size_t)warp * NHW);
    float4 a = row4[lane];
    float s = (a.x + a.y) + (a.z + a.w);
    if (lane < 17) {
        float4 b4 = row4[32 + lane];
        s += (b4.x + b4.y) + (b4.z + b4.w);
    }
#pragma unroll
    for (int o = 16; o; o >>= 1) s += __shfl_xor_sync(0xffffffffu, s, o);
    if (lane == 0) g_pooled[warp] = s * (1.0f / 196.0f);
}

// ---------------------------------------------------------------------------
// Kernel 2: routing. One block = 16 batch rows, 256 threads.
// Phase 1: [16,512] @ [512,64] x2 with W reused 16x per load.
// Phase 2: one warp per 2 rows: softmax + noise branch + top-8 + renorm.
// ---------------------------------------------------------------------------
__global__ __launch_bounds__(256) void router_kernel(
    const float* __restrict__ noise,
    const float* __restrict__ Wr, const float* __restrict__ br,
    const float* __restrict__ Wn, const float* __restrict__ bn,
    float* __restrict__ out)
{
    __shared__ float sp[ROWS][NC];      // 32 KB pooled tile
    __shared__ float sLog[ROWS][NE];    // 4 KB route logits
    __shared__ float sNse[ROWS][NE];    // 4 KB noise logits

    const int tid = threadIdx.x;
    const int b0  = blockIdx.x * ROWS;

    // load pooled tile (coalesced)
    for (int i = tid; i < ROWS * NC; i += 256)
        sp[i / NC][i % NC] = g_pooled[(size_t)b0 * NC + i];
    __syncthreads();

    // GEMM phase: thread = (expert e, quad lane q); q strides the K dim by 4
    const int e = tid >> 2;
    const int q = tid & 3;
    float accR[ROWS], accN[ROWS];
#pragma unroll
    for (int r = 0; r < ROWS; r++) { accR[r] = 0.0f; accN[r] = 0.0f; }

    const float* wr = Wr + e * NC;
    const float* wn = Wn + e * NC;
    for (int i = q; i < NC; i += 4) {
        float a = __ldg(&wr[i]);
        float b = __ldg(&wn[i]);
#pragma unroll
        for (int r = 0; r < ROWS; r++) {
            float p = sp[r][i];
            accR[r] = fmaf(p, a, accR[r]);
            accN[r] = fmaf(p, b, accN[r]);
        }
    }
    // reduce across the quad (lanes q=0..3 of the same expert)
#pragma unroll
    for (int r = 0; r < ROWS; r++) {
        accR[r] += __shfl_xor_sync(0xffffffffu, accR[r], 1);
        accR[r] += __shfl_xor_sync(0xffffffffu, accR[r], 2);
        accN[r] += __shfl_xor_sync(0xffffffffu, accN[r], 1);
        accN[r] += __shfl_xor_sync(0xffffffffu, accN[r], 2);
    }
    if (q == 0) {
        float brv = br[e], bnv = bn[e];
#pragma unroll
        for (int r = 0; r < ROWS; r++) {
            sLog[r][e] = accR[r] + brv;
            sNse[r][e] = accN[r] + bnv;
        }
    }
    __syncthreads();

    // Postprocess: warp w handles rows 2w, 2w+1. Each lane owns experts lane, lane+32.
    const int wid  = tid >> 5;
    const int lane = tid & 31;

    float* out_rtr = out;                       // [B,8] router_output
    float* out_idx = out + (size_t)NB * TOPK;   // [B,8] indices (as float)
    float* out_nzy = out + (size_t)2 * NB * TOPK; // [B,64] noisy_logits

#pragma unroll
    for (int rr = 0; rr < 2; rr++) {
        const int r = wid * 2 + rr;
        const int b = b0 + r;

        float lg0 = sLog[r][lane],      lg1 = sLog[r][lane + 32];
        float nl0 = sNse[r][lane],      nl1 = sNse[r][lane + 32];

        // softmax(route logits) over 64
        float m = fmaxf(lg0, lg1);
#pragma unroll
        for (int o = 16; o; o >>= 1) m = fmaxf(m, __shfl_xor_sync(0xffffffffu, m, o));
        float e0 = __expf(lg0 - m), e1 = __expf(lg1 - m);
        float s = e0 + e1;
#pragma unroll
        for (int o = 16; o; o >>= 1) s += __shfl_xor_sync(0xffffffffu, s, o);
        float inv = __frcp_rn(s);
        float smL0 = e0 * inv, smL1 = e1 * inv;

        // noise branch: z = noise * softplus(noise_logits); softmax(z) over 64
        float sp0 = fmaxf(nl0, 0.0f) + log1pf(__expf(-fabsf(nl0)));
        float sp1 = fmaxf(nl1, 0.0f) + log1pf(__expf(-fabsf(nl1)));
        float z0 = noise[(size_t)b * NE + lane]      * sp0;
        float z1 = noise[(size_t)b * NE + lane + 32] * sp1;
        float mn = fmaxf(z0, z1);
#pragma unroll
        for (int o = 16; o; o >>= 1) mn = fmaxf(mn, __shfl_xor_sync(0xffffffffu, mn, o));
        float f0 = __expf(z0 - mn), f1 = __expf(z1 - mn);
        float sn = f0 + f1;
#pragma unroll
        for (int o = 16; o; o >>= 1) sn += __shfl_xor_sync(0xffffffffu, sn, o);
        float invn = __frcp_rn(sn);

        float noisy0 = smL0 + f0 * invn;
        float noisy1 = smL1 + f1 * invn;

        out_nzy[(size_t)b * NE + lane]      = noisy0;
        out_nzy[(size_t)b * NE + lane + 32] = noisy1;

        // top-8: iterative warp argmax, tie-break = lowest index (matches lax.top_k)
        float v0 = noisy0, v1 = noisy1;
        float topv[TOPK];
        int   topi[TOPK];
#pragma unroll
        for (int k = 0; k < TOPK; k++) {
            float bv; int bi;
            if (v0 >= v1) { bv = v0; bi = lane; }      // >= picks lower index on tie
            else          { bv = v1; bi = lane + 32; }
#pragma unroll
            for (int o = 16; o; o >>= 1) {
                float ov = __shfl_xor_sync(0xffffffffu, bv, o);
                int   oi = __shfl_xor_sync(0xffffffffu, bi, o);
                if (ov > bv || (ov == bv && oi < bi)) { bv = ov; bi = oi; }
            }
            topv[k] = bv; topi[k] = bi;
            if      (bi == lane)      v0 = -INFINITY;
            else if (bi == lane + 32) v1 = -INFINITY;
        }

        // softmax over the 8 selected (topv[0] is the max; computed redundantly per lane)
        float ssum = 0.0f, ev[TOPK];
#pragma unroll
        for (int k = 0; k < TOPK; k++) { ev[k] = __expf(topv[k] - topv[0]); ssum += ev[k]; }
        float invt = __frcp_rn(ssum);

#pragma unroll
        for (int k = 0; k < TOPK; k++) {
            if (lane == k) {
                out_rtr[(size_t)b * TOPK + k] = ev[k] * invt;
                out_idx[(size_t)b * TOPK + k] = (float)topi[k];
            }
        }
    }
}

// ---------------------------------------------------------------------------
extern "C" void kernel_launch(void* const* d_in, const int* in_sizes, int n_in,
                              void* d_out, int out_size) {
    const float* mh      = (const float*)d_in[0];  // [4096,512,14,14]
    const float* noise   = (const float*)d_in[1];  // [4096,64]
    const float* W_route = (const float*)d_in[2];  // [64,512]
    const float* b_route = (const float*)d_in[3];  // [64]
    const float* W_noise = (const float*)d_in[4];  // [64,512]
    const float* b_noise = (const float*)d_in[5];  // [64]
    float* out = (float*)d_out;

    // Kernel 1: pool — one warp per (b,c), 8 warps per block
    int nwarps = NB * NC;
    pool_kernel<<<nwarps / 8, 256>>>(mh);

    // Kernel 2: router — 16 rows per block
    router_kernel<<<NB / ROWS, 256>>>(noise, W_route, b_route, W_noise, b_noise, out);
}